// round 15
// baseline (speedup 1.0000x reference)
#include <cuda_runtime.h>
#include <cuda_fp16.h>
#include <cstdint>

#define EPS 1e-5f

constexpr int E_MAX = 1600000;
constexpr int N_MAX = 100000;

// ---------------- scratch (device globals; no allocations allowed) ----------
__device__ __half g_h1[(size_t)E_MAX * 64];     // edge lin1 output (pre-BN), fp16
__device__ float g_spre[(size_t)N_MAX * 64];    // per-node MEAN of relu(bn(h1))
__device__ __half g_o1h[(size_t)N_MAX * 64];    // node lin (pre-BN), fp16
__device__ float g_ind[N_MAX];                  // deg>0 indicator
__device__ float g_stats[256];                  // [sum1|sq1|sum3|sq3] x64
__device__ float g_w23[64 * 64];                // w2 @ w3[3:]
__device__ float g_bb[64];                      // b2 @ w3[3:]
__device__ uint4 g_wpk[1480];                   // w1 fp16 packed {h0,h1,l0,l1}
__device__ uint4 g_wpkB[1480];                  // node1 B (w23|w3[0:3]) packed
__device__ uint4 g_wpkC[1480];                  // w4 packed
__device__ int   g_off[N_MAX + 1];              // CSR offsets
__device__ int   g_cur[N_MAX];                  // fill cursors
__device__ int   g_eidx[E_MAX];                 // edge ids grouped by dest
__device__ int   g_bsum[512];                   // scan block sums
__device__ int   g_is64;                        // edge_index dtype flag

// ---------------- helpers ---------------------------------------------------
__device__ __forceinline__ long long load_index(const void* ei, size_t pos, int is64) {
    return is64 ? ((const long long*)ei)[pos] : (long long)((const int*)ei)[pos];
}

__device__ __forceinline__ unsigned packh(float lo, float hi) {
    unsigned d;
    asm("cvt.rn.f16x2.f32 %0, %1, %2;" : "=r"(d) : "f"(hi), "f"(lo));
    return d;
}
__device__ __forceinline__ float2 h2f(unsigned p) {
    return __half22float2(*(__half2*)&p);
}

__device__ __forceinline__ void mma_f16(float c[4], const unsigned a[4], const unsigned b[2]) {
    asm volatile(
        "mma.sync.aligned.m16n8k16.row.col.f32.f16.f16.f32 "
        "{%0,%1,%2,%3}, {%4,%5,%6,%7}, {%8,%9}, {%0,%1,%2,%3};"
        : "+f"(c[0]), "+f"(c[1]), "+f"(c[2]), "+f"(c[3])
        : "r"(a[0]), "r"(a[1]), "r"(a[2]), "r"(a[3]), "r"(b[0]), "r"(b[1]));
}

// shared 5-ks asymmetric-fp16 mainloop (M=32/warp): A in aS2 (stride 40 u32), B in wS.
__device__ __forceinline__ void mma_mainloop(const unsigned* aS2, const uint4* wS,
                                             int m0, int nw, int q, int r,
                                             float C[2][4][4])
{
    #pragma unroll
    for (int ks = 0; ks < 5; ++ks) {
        const unsigned* arow = aS2 + (m0 + r) * 40 + (ks * 4 + q) * 2;
        uint2 a0 = *(const uint2*)(arow);
        uint2 a1 = *(const uint2*)(arow + 8 * 40);
        uint2 a2 = *(const uint2*)(arow + 16 * 40);
        uint2 a3 = *(const uint2*)(arow + 24 * 40);
        const uint4* bp = wS + ks * 296 + q * 74 + r * 9 + nw * 4;
        uint4 B0 = bp[0], B1 = bp[1], B2 = bp[2], B3 = bp[3];
        unsigned Ah0[4] = {a0.x, a1.x, a0.y, a1.y};
        unsigned Ah1[4] = {a2.x, a3.x, a2.y, a3.y};
        {
            unsigned Bh[2] = {B0.x, B0.y}, Bl[2] = {B0.z, B0.w};
            mma_f16(C[0][0], Ah0, Bh); mma_f16(C[0][0], Ah0, Bl);
            mma_f16(C[1][0], Ah1, Bh); mma_f16(C[1][0], Ah1, Bl);
        }
        {
            unsigned Bh[2] = {B1.x, B1.y}, Bl[2] = {B1.z, B1.w};
            mma_f16(C[0][1], Ah0, Bh); mma_f16(C[0][1], Ah0, Bl);
            mma_f16(C[1][1], Ah1, Bh); mma_f16(C[1][1], Ah1, Bl);
        }
        {
            unsigned Bh[2] = {B2.x, B2.y}, Bl[2] = {B2.z, B2.w};
            mma_f16(C[0][2], Ah0, Bh); mma_f16(C[0][2], Ah0, Bl);
            mma_f16(C[1][2], Ah1, Bh); mma_f16(C[1][2], Ah1, Bl);
        }
        {
            unsigned Bh[2] = {B3.x, B3.y}, Bl[2] = {B3.z, B3.w};
            mma_f16(C[0][3], Ah0, Bh); mma_f16(C[0][3], Ah0, Bl);
            mma_f16(C[1][3], Ah1, Bh); mma_f16(C[1][3], Ah1, Bl);
        }
    }
}

// ---------------- weight packers --------------------------------------------
__device__ __forceinline__ float wval(const float* w1, int k, int n) {
    if (k >= 67) return 0.f;
    int src = (k < 64) ? (k + 3) : (k - 64);
    return w1[src * 64 + n];
}
__device__ __forceinline__ float wvalB(const float* w3, int k, int n) {
    if (k < 64) return g_w23[k * 64 + n];
    if (k < 67) return w3[(k - 64) * 64 + n];
    return 0.f;
}
__device__ __forceinline__ float wvalC(const float* w4, int k, int n) {
    return (k < 64) ? w4[k * 64 + n] : 0.f;
}

#define PACK_LOOP(DST, FETCH, SRC)                                          \
    for (int idx = t; idx < 1280; idx += 256) {                             \
        int ni = idx & 3, half = (idx >> 2) & 1, r = (idx >> 3) & 7;        \
        int q = (idx >> 6) & 3, ks = idx >> 8;                              \
        int n = half * 32 + ni * 8 + r;                                     \
        int p0 = ks * 8 + q, p1 = p0 + 4;                                   \
        float v0 = FETCH(SRC, 2 * p0, n),  v1 = FETCH(SRC, 2 * p0 + 1, n);  \
        float v2 = FETCH(SRC, 2 * p1, n),  v3 = FETCH(SRC, 2 * p1 + 1, n);  \
        unsigned h0 = packh(v0, v1), h1 = packh(v2, v3);                    \
        float2 e0 = h2f(h0), e1 = h2f(h1);                                  \
        unsigned l0 = packh(v0 - e0.x, v1 - e0.y);                          \
        unsigned l1 = packh(v2 - e1.x, v3 - e1.y);                          \
        uint4 out; out.x = h0; out.y = h1; out.z = l0; out.w = l1;          \
        DST[ks * 296 + q * 74 + r * 9 + half * 4 + ni] = out;               \
    }

__global__ void k_prep(const float* __restrict__ w1, const int* __restrict__ ei32)
{
    int t = threadIdx.x;
    if (t == 0) {
        int is64 = 1;
        #pragma unroll
        for (int i = 0; i < 8; ++i) if (ei32[2 * i + 1] != 0) is64 = 0;
        g_is64 = is64;
    }
    PACK_LOOP(g_wpk, wval, w1)
}

__global__ void k_prep2(const float* __restrict__ w2, const float* __restrict__ w3,
                        const float* __restrict__ b2, const float* __restrict__ w4)
{
    int t = threadIdx.x;
    int i = t >> 2, jc = (t & 3) << 4;
    float acc[16];
    #pragma unroll
    for (int j = 0; j < 16; ++j) acc[j] = 0.f;
    for (int k = 0; k < 64; ++k) {
        float a = w2[i * 64 + k];
        const float* wr = w3 + (3 + k) * 64 + jc;
        #pragma unroll
        for (int j = 0; j < 16; ++j) acc[j] = fmaf(a, wr[j], acc[j]);
    }
    for (int j = 0; j < 16; ++j) g_w23[i * 64 + jc + j] = acc[j];
    if (t < 64) {
        float s = 0.f;
        for (int k = 0; k < 64; ++k) s = fmaf(b2[k], w3[(3 + k) * 64 + t], s);
        g_bb[t] = s;
    }
    __syncthreads();
    PACK_LOOP(g_wpkB, wvalB, w3)
    PACK_LOOP(g_wpkC, wvalC, w4)
}

// ---------------- CSR build --------------------------------------------------
__global__ void k_hist(const void* __restrict__ ei, int E) {
    int e = blockIdx.x * 256 + threadIdx.x;
    if (e >= E) return;
    int c = (int)load_index(ei, (size_t)E + e, g_is64);
    atomicAdd(&g_off[c], 1);
}

__global__ void k_scan1(int N) {
    __shared__ int s[1024];
    int t = threadIdx.x, i = blockIdx.x * 1024 + t;
    int v = (i < N) ? g_off[i] : 0;
    s[t] = v; __syncthreads();
    #pragma unroll
    for (int off = 1; off < 1024; off <<= 1) {
        int x = s[t];
        int y = (t >= off) ? s[t - off] : 0;
        __syncthreads();
        s[t] = x + y;
        __syncthreads();
    }
    int incl = s[t];
    if (i < N) g_off[i] = incl - v;
    if (t == 1023) g_bsum[blockIdx.x] = incl;
}

__global__ void k_scan2(int G) {
    __shared__ int s[512];
    int t = threadIdx.x;
    int v = (t < G) ? g_bsum[t] : 0;
    s[t] = v; __syncthreads();
    #pragma unroll
    for (int off = 1; off < 512; off <<= 1) {
        int x = s[t];
        int y = (t >= off) ? s[t - off] : 0;
        __syncthreads();
        s[t] = x + y;
        __syncthreads();
    }
    if (t < G) g_bsum[t] = s[t] - v;
}

__global__ void k_scan3(int N, int E) {
    int i = blockIdx.x * 1024 + threadIdx.x;
    if (i < N) {
        int v = g_off[i] + g_bsum[blockIdx.x];
        g_off[i] = v;
        g_cur[i] = v;
    }
    if (i == 0) g_off[N] = E;
}

__global__ void k_fill(const void* __restrict__ ei, int E) {
    int e = blockIdx.x * 256 + threadIdx.x;
    if (e >= E) return;
    int c = (int)load_index(ei, (size_t)E + e, g_is64);
    int pos = atomicAdd(&g_cur[c], 1);
    g_eidx[pos] = e;
}

// ---------------- K1: edge lin1, 256-edge tile, M=64/warp, 3 CTAs/SM --------
__global__ __launch_bounds__(256, 3)
void k_edge(const float* __restrict__ x, const void* __restrict__ ei,
            const float* __restrict__ ea, const float* __restrict__ b1, int E)
{
    extern __shared__ uint4 sm4[];
    uint4* wS = sm4;                              // 1480 uint4
    unsigned* aS2 = (unsigned*)(sm4 + 1480);      // 256 * 40 u32 (reused as hS)
    float* sstat = (float*)(aS2 + 256 * 40);      // 128
    int t = threadIdx.x;
    int lane = t & 31, w = t >> 5;
    int e0 = blockIdx.x * 256;
    int is64 = g_is64;

    for (int i = t; i < 1480; i += 256) wS[i] = g_wpk[i];

    // edge_attr staging: 256 rows x 16 uint2 tasks
    #pragma unroll
    for (int it = 0; it < 16; ++it) {
        int idx = t + it * 256;
        int erow = idx >> 4, j = idx & 15;
        int ks = j >> 2, qq = j & 3;
        float2 f0 = make_float2(0.f, 0.f), f1 = make_float2(0.f, 0.f);
        if (e0 + erow < E) {
            const float2* rp = (const float2*)(ea + (size_t)(e0 + erow) * 64 + ks * 16 + 2 * qq);
            f0 = rp[0];
            f1 = rp[4];
        }
        *(uint2*)(aS2 + erow * 40 + 2 * j) = make_uint2(packh(f0.x, f0.y), packh(f1.x, f1.y));
    }
    // x gather: one row per thread (256 rows)
    {
        int e = e0 + t;
        float x0 = 0.f, x1 = 0.f, x2 = 0.f;
        if (e < E) {
            long long r = load_index(ei, (size_t)e, is64);
            const float* xp = x + r * 3;
            x0 = xp[0]; x1 = xp[1]; x2 = xp[2];
        }
        unsigned* ap = aS2 + t * 40 + 32;
        *(uint2*)(ap + 0) = make_uint2(packh(x0, x1), 0u);
        *(uint2*)(ap + 2) = make_uint2(packh(x2, 0.f), 0u);
        *(uint2*)(ap + 4) = make_uint2(0u, 0u);
        *(uint2*)(ap + 6) = make_uint2(0u, 0u);
        if (t < 128) sstat[t] = 0.f;
    }
    __syncthreads();

    int q = lane & 3, r = lane >> 2;
    int mw = w >> 1, nw = w & 1;
    int m0 = mw * 64, nb = nw * 32;

    float C[4][4][4];
    #pragma unroll
    for (int mi = 0; mi < 4; ++mi)
        #pragma unroll
        for (int ni = 0; ni < 4; ++ni)
            #pragma unroll
            for (int j = 0; j < 4; ++j) C[mi][ni][j] = 0.f;

    #pragma unroll
    for (int ks = 0; ks < 5; ++ks) {
        const uint4* bp = wS + ks * 296 + q * 74 + r * 9 + nw * 4;
        uint4 B0 = bp[0], B1 = bp[1], B2 = bp[2], B3 = bp[3];
        unsigned Bh0[2] = {B0.x, B0.y}, Bl0[2] = {B0.z, B0.w};
        unsigned Bh1[2] = {B1.x, B1.y}, Bl1[2] = {B1.z, B1.w};
        unsigned Bh2[2] = {B2.x, B2.y}, Bl2[2] = {B2.z, B2.w};
        unsigned Bh3[2] = {B3.x, B3.y}, Bl3[2] = {B3.z, B3.w};
        #pragma unroll
        for (int mi = 0; mi < 4; ++mi) {
            const unsigned* arow = aS2 + (m0 + mi * 16 + r) * 40 + (ks * 4 + q) * 2;
            uint2 a0 = *(const uint2*)(arow);
            uint2 a1 = *(const uint2*)(arow + 8 * 40);
            unsigned Ah[4] = {a0.x, a1.x, a0.y, a1.y};
            mma_f16(C[mi][0], Ah, Bh0); mma_f16(C[mi][0], Ah, Bl0);
            mma_f16(C[mi][1], Ah, Bh1); mma_f16(C[mi][1], Ah, Bl1);
            mma_f16(C[mi][2], Ah, Bh2); mma_f16(C[mi][2], Ah, Bl2);
            mma_f16(C[mi][3], Ah, Bh3); mma_f16(C[mi][3], Ah, Bl3);
        }
    }

    float bv[4][2];
    #pragma unroll
    for (int ni = 0; ni < 4; ++ni) {
        bv[ni][0] = __ldg(b1 + nb + ni * 8 + 2 * q);
        bv[ni][1] = __ldg(b1 + nb + ni * 8 + 2 * q + 1);
    }
    float cs[4][2], cq[4][2];
    #pragma unroll
    for (int ni = 0; ni < 4; ++ni) { cs[ni][0]=cs[ni][1]=cq[ni][0]=cq[ni][1]=0.f; }

    __syncthreads();   // A tile dead; reuse aS2 as output tile (stride 36 words)

    #pragma unroll
    for (int mi = 0; mi < 4; ++mi)
        #pragma unroll
        for (int half = 0; half < 2; ++half) {
            int rowl = m0 + mi * 16 + half * 8 + r;
            int e = e0 + rowl;
            if (e < E) {
                unsigned* hp = aS2 + rowl * 36 + (nb >> 1);
                #pragma unroll
                for (int ni = 0; ni < 4; ++ni) {
                    float v0 = C[mi][ni][half * 2 + 0] + bv[ni][0];
                    float v1 = C[mi][ni][half * 2 + 1] + bv[ni][1];
                    __half2 hh = __floats2half2_rn(v0, v1);
                    hp[ni * 4 + q] = *(unsigned*)&hh;
                    float2 qv = __half22float2(hh);
                    cs[ni][0] += qv.x; cs[ni][1] += qv.y;
                    cq[ni][0] += qv.x * qv.x; cq[ni][1] += qv.y * qv.y;
                }
            }
        }
    #pragma unroll
    for (int ni = 0; ni < 4; ++ni)
        #pragma unroll
        for (int j = 0; j < 2; ++j) {
            #pragma unroll
            for (int off = 4; off <= 16; off <<= 1) {
                cs[ni][j] += __shfl_xor_sync(0xffffffffu, cs[ni][j], off);
                cq[ni][j] += __shfl_xor_sync(0xffffffffu, cq[ni][j], off);
            }
        }
    if (lane < 4) {
        #pragma unroll
        for (int ni = 0; ni < 4; ++ni) {
            int col = nb + ni * 8 + 2 * lane;
            atomicAdd(&sstat[col],          cs[ni][0]);
            atomicAdd(&sstat[col + 1],      cs[ni][1]);
            atomicAdd(&sstat[64 + col],     cq[ni][0]);
            atomicAdd(&sstat[64 + col + 1], cq[ni][1]);
        }
    }
    __syncthreads();

    // coalesced h1 store: 8 threads per 128B row
    #pragma unroll
    for (int it = 0; it < 8; ++it) {
        int idx = t + it * 256;
        int row = idx >> 3, c = idx & 7;
        int e = e0 + row;
        if (e < E) {
            uint4 v = *(const uint4*)(aS2 + row * 36 + c * 4);
            *(uint4*)(g_h1 + (size_t)e * 64 + c * 8) = v;
        }
    }
    if (t < 128) atomicAdd(&g_stats[t], sstat[t]);
}

// ---------------- K3: gather-aggregate (1 warp / node, fp32 reg accum) ------
__global__ __launch_bounds__(256)
void k_gather(const float* __restrict__ g1, const float* __restrict__ be1,
              int N, float invE)
{
    __shared__ float a1s[64], c1s[64];
    int t = threadIdx.x;
    if (t < 64) {
        float m = g_stats[t] * invE;
        float v = g_stats[64 + t] * invE - m * m;
        float a = g1[t] * rsqrtf(v + EPS);
        a1s[t] = a;
        c1s[t] = be1[t] - m * a;
    }
    __syncthreads();
    int w = t >> 5, lane = t & 31;
    int n = blockIdx.x * 8 + w;
    if (n >= N) return;
    int beg = g_off[n], end = g_off[n + 1];
    int deg = end - beg;
    float a0 = a1s[2 * lane], a1v = a1s[2 * lane + 1];
    float c0 = c1s[2 * lane], c1v = c1s[2 * lane + 1];
    float acc0 = 0.f, acc1 = 0.f;
    for (int base = beg; base < end; base += 32) {
        int cnt = min(32, end - base);
        int eid = (lane < cnt) ? g_eidx[base + lane] : 0;
        for (int j = 0; j < cnt; ++j) {
            int e = __shfl_sync(0xffffffffu, eid, j);
            __half2 hv = *(const __half2*)(g_h1 + (size_t)e * 64 + 2 * lane);
            float2 f = __half22float2(hv);
            acc0 += fmaxf(fmaf(f.x, a0, c0), 0.f);
            acc1 += fmaxf(fmaf(f.y, a1v, c1v), 0.f);
        }
    }
    float rcp = 1.f / fmaxf((float)deg, 1.f);
    *(float2*)(g_spre + (size_t)n * 64 + 2 * lane) = make_float2(acc0 * rcp, acc1 * rcp);
    if (lane == 0) g_ind[n] = (deg > 0) ? 1.f : 0.f;
}

// ---------------- K4: node lin via fp16 mma + BN stats ----------------------
__global__ __launch_bounds__(256, 3)
void k_node1(const float* __restrict__ x, const float* __restrict__ b3, int N)
{
    extern __shared__ uint4 sm4[];
    uint4* wS = sm4;                              // 1480 uint4
    unsigned* aS2 = (unsigned*)(sm4 + 1480);      // 128 * 40 u32
    float* sstat = (float*)(aS2 + 128 * 40);      // 128
    float* indS  = sstat + 128;                   // 128
    int t = threadIdx.x;
    int lane = t & 31, w = t >> 5;
    int n0 = blockIdx.x * 128;

    for (int i = t; i < 1480; i += 256) wS[i] = g_wpkB[i];

    #pragma unroll
    for (int it = 0; it < 8; ++it) {
        int idx = t + it * 256;
        int erow = idx >> 4, j = idx & 15;
        int ks = j >> 2, qq = j & 3;
        float2 f0 = make_float2(0.f, 0.f), f1 = make_float2(0.f, 0.f);
        if (n0 + erow < N) {
            const float2* rp = (const float2*)(g_spre + (size_t)(n0 + erow) * 64 + ks * 16 + 2 * qq);
            f0 = rp[0];
            f1 = rp[4];
        }
        *(uint2*)(aS2 + erow * 40 + 2 * j) = make_uint2(packh(f0.x, f0.y), packh(f1.x, f1.y));
    }
    if (t < 128) {
        int n = n0 + t;
        float x0 = 0.f, x1 = 0.f, x2 = 0.f, ind = 0.f;
        if (n < N) {
            x0 = x[n * 3]; x1 = x[n * 3 + 1]; x2 = x[n * 3 + 2];
            ind = g_ind[n];
        }
        unsigned* ap = aS2 + t * 40 + 32;
        *(uint2*)(ap + 0) = make_uint2(packh(x0, x1), 0u);
        *(uint2*)(ap + 2) = make_uint2(packh(x2, 0.f), 0u);
        *(uint2*)(ap + 4) = make_uint2(0u, 0u);
        *(uint2*)(ap + 6) = make_uint2(0u, 0u);
        sstat[t] = 0.f;
        indS[t] = ind;
    }
    __syncthreads();

    int q = lane & 3, r = lane >> 2;
    int mw = w >> 1, nw = w & 1;
    int m0 = mw * 32, nb = nw * 32;

    float C[2][4][4];
    #pragma unroll
    for (int mi = 0; mi < 2; ++mi)
        #pragma unroll
        for (int ni = 0; ni < 4; ++ni)
            #pragma unroll
            for (int j = 0; j < 4; ++j) C[mi][ni][j] = 0.f;

    mma_mainloop(aS2, wS, m0, nw, q, r, C);

    float bv[4][2], bbv[4][2];
    #pragma unroll
    for (int ni = 0; ni < 4; ++ni) {
        int col = nb + ni * 8 + 2 * q;
        bv[ni][0] = __ldg(b3 + col);     bv[ni][1] = __ldg(b3 + col + 1);
        bbv[ni][0] = g_bb[col];          bbv[ni][1] = g_bb[col + 1];
    }
    float cs[4][2], cq[4][2];
    #pragma unroll
    for (int ni = 0; ni < 4; ++ni) { cs[ni][0]=cs[ni][1]=cq[ni][0]=cq[ni][1]=0.f; }

    #pragma unroll
    for (int mi = 0; mi < 2; ++mi)
        #pragma unroll
        for (int half = 0; half < 2; ++half) {
            int rowl = m0 + mi * 16 + half * 8 + r;
            int n = n0 + rowl;
            if (n < N) {
                float ind = indS[rowl];
                __half* hp = g_o1h + (size_t)n * 64 + nb;
                #pragma unroll
                for (int ni = 0; ni < 4; ++ni) {
                    float v0 = C[mi][ni][half * 2 + 0] + bv[ni][0] + ind * bbv[ni][0];
                    float v1 = C[mi][ni][half * 2 + 1] + bv[ni][1] + ind * bbv[ni][1];
                    __half2 hh = __floats2half2_rn(v0, v1);
                    *(__half2*)(hp + ni * 8 + 2 * q) = hh;
                    float2 qv = __half22float2(hh);
                    cs[ni][0] += qv.x; cs[ni][1] += qv.y;
                    cq[ni][0] += qv.x * qv.x; cq[ni][1] += qv.y * qv.y;
                }
            }
        }
    #pragma unroll
    for (int ni = 0; ni < 4; ++ni)
        #pragma unroll
        for (int j = 0; j < 2; ++j) {
            #pragma unroll
            for (int off = 4; off <= 16; off <<= 1) {
                cs[ni][j] += __shfl_xor_sync(0xffffffffu, cs[ni][j], off);
                cq[ni][j] += __shfl_xor_sync(0xffffffffu, cq[ni][j], off);
            }
        }
    if (lane < 4) {
        #pragma unroll
        for (int ni = 0; ni < 4; ++ni) {
            int col = nb + ni * 8 + 2 * lane;
            atomicAdd(&sstat[col],          cs[ni][0]);
            atomicAdd(&sstat[col + 1],      cs[ni][1]);
            atomicAdd(&sstat[64 + col],     cq[ni][0]);
            atomicAdd(&sstat[64 + col + 1], cq[ni][1]);
        }
    }
    __syncthreads();
    if (t < 128) atomicAdd(&g_stats[128 + t], sstat[t]);
}

// ---------------- K6: out = relu(bn(o1)) @ w4 + b4 via fp16 mma -------------
__global__ __launch_bounds__(256, 3)
void k_node2(const float* __restrict__ b4, const float* __restrict__ g3,
             const float* __restrict__ be3, float* __restrict__ out,
             int N, float invN)
{
    extern __shared__ uint4 sm4[];
    uint4* wS = sm4;                              // 1480 uint4
    unsigned* aS2 = (unsigned*)(sm4 + 1480);      // 128 * 40 u32
    float* a3s = (float*)(aS2 + 128 * 40);        // 64
    float* c3s = a3s + 64;                        // 64
    int t = threadIdx.x;
    int lane = t & 31, w = t >> 5;
    int n0 = blockIdx.x * 128;

    for (int i = t; i < 1480; i += 256) wS[i] = g_wpkC[i];
    if (t < 64) {
        float m = g_stats[128 + t] * invN;
        float v = g_stats[192 + t] * invN - m * m;
        float a = g3[t] * rsqrtf(v + EPS);
        a3s[t] = a;
        c3s[t] = be3[t] - m * a;
    }
    __syncthreads();

    #pragma unroll
    for (int it = 0; it < 8; ++it) {
        int idx = t + it * 256;
        int erow = idx >> 4, j = idx & 15;
        int ks = j >> 2, qq = j & 3;
        float2 f0 = make_float2(0.f, 0.f), f1 = make_float2(0.f, 0.f);
        if (n0 + erow < N) {
            const unsigned* orow = (const unsigned*)(g_o1h + (size_t)(n0 + erow) * 64);
            int p0 = ks * 8 + qq;
            float2 e0 = h2f(orow[p0]);
            float2 e1 = h2f(orow[p0 + 4]);
            int k0 = 2 * p0, k1 = 2 * p0 + 8;
            f0.x = fmaxf(fmaf(e0.x, a3s[k0],     c3s[k0]),     0.f);
            f0.y = fmaxf(fmaf(e0.y, a3s[k0 + 1], c3s[k0 + 1]), 0.f);
            f1.x = fmaxf(fmaf(e1.x, a3s[k1],     c3s[k1]),     0.f);
            f1.y = fmaxf(fmaf(e1.y, a3s[k1 + 1], c3s[k1 + 1]), 0.f);
        }
        *(uint2*)(aS2 + erow * 40 + 2 * j) = make_uint2(packh(f0.x, f0.y), packh(f1.x, f1.y));
    }
    if (t < 128) {
        unsigned* ap = aS2 + t * 40 + 32;
        *(uint2*)(ap + 0) = make_uint2(0u, 0u);
        *(uint2*)(ap + 2) = make_uint2(0u, 0u);
        *(uint2*)(ap + 4) = make_uint2(0u, 0u);
        *(uint2*)(ap + 6) = make_uint2(0u, 0u);
    }
    __syncthreads();

    int q = lane & 3, r = lane >> 2;
    int mw = w >> 1, nw = w & 1;
    int m0 = mw * 32, nb = nw * 32;

    float C[2][4][4];
    #pragma unroll
    for (int mi = 0; mi < 2; ++mi)
        #pragma unroll
        for (int ni = 0; ni < 4; ++ni)
            #pragma unroll
            for (int j = 0; j < 4; ++j) C[mi][ni][j] = 0.f;

    mma_mainloop(aS2, wS, m0, nw, q, r, C);

    float bv[4][2];
    #pragma unroll
    for (int ni = 0; ni < 4; ++ni) {
        bv[ni][0] = __ldg(b4 + nb + ni * 8 + 2 * q);
        bv[ni][1] = __ldg(b4 + nb + ni * 8 + 2 * q + 1);
    }
    #pragma unroll
    for (int mi = 0; mi < 2; ++mi)
        #pragma unroll
        for (int half = 0; half < 2; ++half) {
            int n = n0 + m0 + mi * 16 + half * 8 + r;
            if (n < N) {
                float* op = out + (size_t)n * 64 + nb;
                #pragma unroll
                for (int ni = 0; ni < 4; ++ni) {
                    float v0 = C[mi][ni][half * 2 + 0] + bv[ni][0];
                    float v1 = C[mi][ni][half * 2 + 1] + bv[ni][1];
                    *(float2*)(op + ni * 8 + 2 * q) = make_float2(v0, v1);
                }
            }
        }
}

// ---------------- host ------------------------------------------------------
extern "C" void kernel_launch(void* const* d_in, const int* in_sizes, int n_in,
                              void* d_out, int out_size)
{
    const float* x   = (const float*)d_in[0];
    const void*  ei  = d_in[1];
    const float* ea  = (const float*)d_in[2];
    const float* w1  = (const float*)d_in[5];
    const float* b1  = (const float*)d_in[6];
    const float* g1  = (const float*)d_in[7];
    const float* be1 = (const float*)d_in[8];
    const float* w2  = (const float*)d_in[9];
    const float* b2  = (const float*)d_in[10];
    const float* w3  = (const float*)d_in[11];
    const float* b3  = (const float*)d_in[12];
    const float* g3  = (const float*)d_in[13];
    const float* be3 = (const float*)d_in[14];
    const float* w4  = (const float*)d_in[15];
    const float* b4  = (const float*)d_in[16];
    int N = in_sizes[0] / 3;
    int E = in_sizes[2] / 64;

    static cudaStream_t s2 = nullptr;
    static cudaEvent_t evFork = nullptr, evJoin = nullptr;
    if (s2 == nullptr) {
        cudaStreamCreateWithFlags(&s2, cudaStreamNonBlocking);
        cudaEventCreateWithFlags(&evFork, cudaEventDisableTiming);
        cudaEventCreateWithFlags(&evJoin, cudaEventDisableTiming);
    }

    const int SMEM_K1 = 1480 * 16 + 256 * 40 * 4 + 128 * 4;               // 65152
    const int SMEM_K4 = 1480 * 16 + 128 * 40 * 4 + 256 * 4;               // 45184
    const int SMEM_K6 = 1480 * 16 + 128 * 40 * 4 + 128 * 4;               // 44672

    cudaFuncSetAttribute(k_edge,  cudaFuncAttributeMaxDynamicSharedMemorySize, SMEM_K1);
    cudaFuncSetAttribute(k_node1, cudaFuncAttributeMaxDynamicSharedMemorySize, SMEM_K4);
    cudaFuncSetAttribute(k_node2, cudaFuncAttributeMaxDynamicSharedMemorySize, SMEM_K6);

    void *p_stats, *p_off;
    cudaGetSymbolAddress(&p_stats, g_stats);
    cudaGetSymbolAddress(&p_off,   g_off);

    int G1 = (N + 1023) / 1024;

    // main stream: stats memset + w1 pack (+dtype detect), then fork
    cudaMemsetAsync(p_stats, 0, 256 * sizeof(float), 0);                  // slot 0
    k_prep<<<1, 256>>>(w1, (const int*)ei);                               // slot 1
    cudaEventRecord(evFork, 0);
    cudaStreamWaitEvent(s2, evFork, 0);

    // side stream: node-weight prep + CSR front half (submitted before k_edge
    // so k_edge lands at global launch slot 5 for ncu -s 5 -c 1)
    k_prep2<<<1, 256, 0, s2>>>(w2, w3, b2, w4);                           // slot 2
    cudaMemsetAsync(p_off, 0, (size_t)(N + 1) * sizeof(int), s2);         // slot 3
    k_hist<<<(E + 255) / 256, 256, 0, s2>>>(ei, E);                       // slot 4

    // main stream: edge GEMM (the long pole)                              // slot 5
    k_edge<<<(E + 255) / 256, 256, SMEM_K1>>>(x, ei, ea, b1, E);

    // side stream: CSR back half
    k_scan1<<<G1, 1024, 0, s2>>>(N);
    k_scan2<<<1, 512, 0, s2>>>(G1);
    k_scan3<<<G1, 1024, 0, s2>>>(N, E);
    k_fill<<<(E + 255) / 256, 256, 0, s2>>>(ei, E);
    cudaEventRecord(evJoin, s2);

    // join, then aggregate + node MLP
    cudaStreamWaitEvent(0, evJoin, 0);
    k_gather<<<(N + 7) / 8, 256>>>(g1, be1, N, 1.f / (float)E);
    k_node1<<<(N + 127) / 128, 256, SMEM_K4>>>(x, b3, N);
    k_node2<<<(N + 127) / 128, 256, SMEM_K6>>>(b4, g3, be3, (float*)d_out, N, 1.f / (float)N);
}

// round 16
// speedup vs baseline: 1.0712x; 1.0712x over previous
#include <cuda_runtime.h>
#include <cuda_fp16.h>
#include <cstdint>

#define EPS 1e-5f

constexpr int E_MAX = 1600000;
constexpr int N_MAX = 100000;

// ---------------- scratch (device globals; no allocations allowed) ----------
__device__ __half g_h1[(size_t)E_MAX * 64];     // edge lin1 output (pre-BN), fp16
__device__ unsigned g_spreP[(size_t)N_MAX * 32];// per-node mean, fp16x2 packed, frag order
__device__ __half g_o1h[(size_t)N_MAX * 64];    // node lin (pre-BN), fp16
__device__ float g_ind[N_MAX];                  // deg>0 indicator
__device__ float g_stats[256];                  // [sum1|sq1|sum3|sq3] x64
__device__ float g_w23[64 * 64];                // w2 @ w3[3:]
__device__ float g_bb[64];                      // b2 @ w3[3:]
__device__ uint4 g_wpk[1480];                   // w1 fp16 packed {h0,h1,l0,l1}
__device__ uint4 g_wpkB[1480];                  // node1 B (w23|w3[0:3]) packed
__device__ uint4 g_wpkC[1480];                  // w4 packed
__device__ int   g_off[N_MAX + 1];              // CSR offsets
__device__ int   g_cur[N_MAX];                  // fill cursors
__device__ int   g_eidx[E_MAX];                 // edge ids grouped by dest
__device__ int   g_bsum[512];                   // scan block sums
__device__ int   g_is64;                        // edge_index dtype flag

// ---------------- helpers ---------------------------------------------------
__device__ __forceinline__ long long load_index(const void* ei, size_t pos, int is64) {
    return is64 ? ((const long long*)ei)[pos] : (long long)((const int*)ei)[pos];
}

__device__ __forceinline__ unsigned packh(float lo, float hi) {
    unsigned d;
    asm("cvt.rn.f16x2.f32 %0, %1, %2;" : "=r"(d) : "f"(hi), "f"(lo));
    return d;
}
__device__ __forceinline__ float2 h2f(unsigned p) {
    return __half22float2(*(__half2*)&p);
}

__device__ __forceinline__ void mma_f16(float c[4], const unsigned a[4], const unsigned b[2]) {
    asm volatile(
        "mma.sync.aligned.m16n8k16.row.col.f32.f16.f16.f32 "
        "{%0,%1,%2,%3}, {%4,%5,%6,%7}, {%8,%9}, {%0,%1,%2,%3};"
        : "+f"(c[0]), "+f"(c[1]), "+f"(c[2]), "+f"(c[3])
        : "r"(a[0]), "r"(a[1]), "r"(a[2]), "r"(a[3]), "r"(b[0]), "r"(b[1]));
}

// shared 5-ks asymmetric-fp16 mainloop (M=32/warp): A in aS2 (stride 40 u32), B in wS.
__device__ __forceinline__ void mma_mainloop(const unsigned* aS2, const uint4* wS,
                                             int m0, int nw, int q, int r,
                                             float C[2][4][4])
{
    #pragma unroll
    for (int ks = 0; ks < 5; ++ks) {
        const unsigned* arow = aS2 + (m0 + r) * 40 + (ks * 4 + q) * 2;
        uint2 a0 = *(const uint2*)(arow);
        uint2 a1 = *(const uint2*)(arow + 8 * 40);
        uint2 a2 = *(const uint2*)(arow + 16 * 40);
        uint2 a3 = *(const uint2*)(arow + 24 * 40);
        const uint4* bp = wS + ks * 296 + q * 74 + r * 9 + nw * 4;
        uint4 B0 = bp[0], B1 = bp[1], B2 = bp[2], B3 = bp[3];
        unsigned Ah0[4] = {a0.x, a1.x, a0.y, a1.y};
        unsigned Ah1[4] = {a2.x, a3.x, a2.y, a3.y};
        {
            unsigned Bh[2] = {B0.x, B0.y}, Bl[2] = {B0.z, B0.w};
            mma_f16(C[0][0], Ah0, Bh); mma_f16(C[0][0], Ah0, Bl);
            mma_f16(C[1][0], Ah1, Bh); mma_f16(C[1][0], Ah1, Bl);
        }
        {
            unsigned Bh[2] = {B1.x, B1.y}, Bl[2] = {B1.z, B1.w};
            mma_f16(C[0][1], Ah0, Bh); mma_f16(C[0][1], Ah0, Bl);
            mma_f16(C[1][1], Ah1, Bh); mma_f16(C[1][1], Ah1, Bl);
        }
        {
            unsigned Bh[2] = {B2.x, B2.y}, Bl[2] = {B2.z, B2.w};
            mma_f16(C[0][2], Ah0, Bh); mma_f16(C[0][2], Ah0, Bl);
            mma_f16(C[1][2], Ah1, Bh); mma_f16(C[1][2], Ah1, Bl);
        }
        {
            unsigned Bh[2] = {B3.x, B3.y}, Bl[2] = {B3.z, B3.w};
            mma_f16(C[0][3], Ah0, Bh); mma_f16(C[0][3], Ah0, Bl);
            mma_f16(C[1][3], Ah1, Bh); mma_f16(C[1][3], Ah1, Bl);
        }
    }
}

// ---------------- weight packers --------------------------------------------
__device__ __forceinline__ float wval(const float* w1, int k, int n) {
    if (k >= 67) return 0.f;
    int src = (k < 64) ? (k + 3) : (k - 64);
    return w1[src * 64 + n];
}
__device__ __forceinline__ float wvalB(const float* w3, int k, int n) {
    if (k < 64) return g_w23[k * 64 + n];
    if (k < 67) return w3[(k - 64) * 64 + n];
    return 0.f;
}
__device__ __forceinline__ float wvalC(const float* w4, int k, int n) {
    return (k < 64) ? w4[k * 64 + n] : 0.f;
}

#define PACK_LOOP(DST, FETCH, SRC)                                          \
    for (int idx = t; idx < 1280; idx += 256) {                             \
        int ni = idx & 3, half = (idx >> 2) & 1, r = (idx >> 3) & 7;        \
        int q = (idx >> 6) & 3, ks = idx >> 8;                              \
        int n = half * 32 + ni * 8 + r;                                     \
        int p0 = ks * 8 + q, p1 = p0 + 4;                                   \
        float v0 = FETCH(SRC, 2 * p0, n),  v1 = FETCH(SRC, 2 * p0 + 1, n);  \
        float v2 = FETCH(SRC, 2 * p1, n),  v3 = FETCH(SRC, 2 * p1 + 1, n);  \
        unsigned h0 = packh(v0, v1), h1 = packh(v2, v3);                    \
        float2 e0 = h2f(h0), e1 = h2f(h1);                                  \
        unsigned l0 = packh(v0 - e0.x, v1 - e0.y);                          \
        unsigned l1 = packh(v2 - e1.x, v3 - e1.y);                          \
        uint4 out; out.x = h0; out.y = h1; out.z = l0; out.w = l1;          \
        DST[ks * 296 + q * 74 + r * 9 + half * 4 + ni] = out;               \
    }

__global__ void k_prep(const float* __restrict__ w1, const int* __restrict__ ei32)
{
    int t = threadIdx.x;
    if (t == 0) {
        int is64 = 1;
        #pragma unroll
        for (int i = 0; i < 8; ++i) if (ei32[2 * i + 1] != 0) is64 = 0;
        g_is64 = is64;
    }
    PACK_LOOP(g_wpk, wval, w1)
}

__global__ void k_prep2(const float* __restrict__ w2, const float* __restrict__ w3,
                        const float* __restrict__ b2, const float* __restrict__ w4)
{
    int t = threadIdx.x;
    int i = t >> 2, jc = (t & 3) << 4;
    float acc[16];
    #pragma unroll
    for (int j = 0; j < 16; ++j) acc[j] = 0.f;
    for (int k = 0; k < 64; ++k) {
        float a = w2[i * 64 + k];
        const float* wr = w3 + (3 + k) * 64 + jc;
        #pragma unroll
        for (int j = 0; j < 16; ++j) acc[j] = fmaf(a, wr[j], acc[j]);
    }
    for (int j = 0; j < 16; ++j) g_w23[i * 64 + jc + j] = acc[j];
    if (t < 64) {
        float s = 0.f;
        for (int k = 0; k < 64; ++k) s = fmaf(b2[k], w3[(3 + k) * 64 + t], s);
        g_bb[t] = s;
    }
    __syncthreads();
    PACK_LOOP(g_wpkB, wvalB, w3)
    PACK_LOOP(g_wpkC, wvalC, w4)
}

// ---------------- CSR build --------------------------------------------------
__global__ void k_hist(const void* __restrict__ ei, int E) {
    int e = blockIdx.x * 256 + threadIdx.x;
    if (e >= E) return;
    int c = (int)load_index(ei, (size_t)E + e, g_is64);
    atomicAdd(&g_off[c], 1);
}

__global__ void k_scan1(int N) {
    __shared__ int s[1024];
    int t = threadIdx.x, i = blockIdx.x * 1024 + t;
    int v = (i < N) ? g_off[i] : 0;
    s[t] = v; __syncthreads();
    #pragma unroll
    for (int off = 1; off < 1024; off <<= 1) {
        int x = s[t];
        int y = (t >= off) ? s[t - off] : 0;
        __syncthreads();
        s[t] = x + y;
        __syncthreads();
    }
    int incl = s[t];
    if (i < N) g_off[i] = incl - v;
    if (t == 1023) g_bsum[blockIdx.x] = incl;
}

__global__ void k_scan2(int G) {
    __shared__ int s[512];
    int t = threadIdx.x;
    int v = (t < G) ? g_bsum[t] : 0;
    s[t] = v; __syncthreads();
    #pragma unroll
    for (int off = 1; off < 512; off <<= 1) {
        int x = s[t];
        int y = (t >= off) ? s[t - off] : 0;
        __syncthreads();
        s[t] = x + y;
        __syncthreads();
    }
    if (t < G) g_bsum[t] = s[t] - v;
}

__global__ void k_scan3(int N, int E) {
    int i = blockIdx.x * 1024 + threadIdx.x;
    if (i < N) {
        int v = g_off[i] + g_bsum[blockIdx.x];
        g_off[i] = v;
        g_cur[i] = v;
    }
    if (i == 0) g_off[N] = E;
}

__global__ void k_fill(const void* __restrict__ ei, int E) {
    int e = blockIdx.x * 256 + threadIdx.x;
    if (e >= E) return;
    int c = (int)load_index(ei, (size_t)E + e, g_is64);
    int pos = atomicAdd(&g_cur[c], 1);
    g_eidx[pos] = e;
}

// ---------------- K1: edge lin1, 256-edge tile, M=64/warp, 2 CTAs/SM --------
__global__ __launch_bounds__(256, 2)
void k_edge(const float* __restrict__ x, const void* __restrict__ ei,
            const float* __restrict__ ea, const float* __restrict__ b1, int E)
{
    extern __shared__ uint4 sm4[];
    uint4* wS = sm4;                              // 1480 uint4
    unsigned* aS2 = (unsigned*)(sm4 + 1480);      // 256 * 40 u32 (reused as hS)
    float* sstat = (float*)(aS2 + 256 * 40);      // 128
    int t = threadIdx.x;
    int lane = t & 31, w = t >> 5;
    int e0 = blockIdx.x * 256;
    int is64 = g_is64;

    for (int i = t; i < 1480; i += 256) wS[i] = g_wpk[i];

    // edge_attr staging: 256 rows x 16 uint2 tasks
    #pragma unroll
    for (int it = 0; it < 16; ++it) {
        int idx = t + it * 256;
        int erow = idx >> 4, j = idx & 15;
        int ks = j >> 2, qq = j & 3;
        float2 f0 = make_float2(0.f, 0.f), f1 = make_float2(0.f, 0.f);
        if (e0 + erow < E) {
            const float2* rp = (const float2*)(ea + (size_t)(e0 + erow) * 64 + ks * 16 + 2 * qq);
            f0 = rp[0];
            f1 = rp[4];
        }
        *(uint2*)(aS2 + erow * 40 + 2 * j) = make_uint2(packh(f0.x, f0.y), packh(f1.x, f1.y));
    }
    // x gather: one row per thread (256 rows)
    {
        int e = e0 + t;
        float x0 = 0.f, x1 = 0.f, x2 = 0.f;
        if (e < E) {
            long long r = load_index(ei, (size_t)e, is64);
            const float* xp = x + r * 3;
            x0 = xp[0]; x1 = xp[1]; x2 = xp[2];
        }
        unsigned* ap = aS2 + t * 40 + 32;
        *(uint2*)(ap + 0) = make_uint2(packh(x0, x1), 0u);
        *(uint2*)(ap + 2) = make_uint2(packh(x2, 0.f), 0u);
        *(uint2*)(ap + 4) = make_uint2(0u, 0u);
        *(uint2*)(ap + 6) = make_uint2(0u, 0u);
        if (t < 128) sstat[t] = 0.f;
    }
    __syncthreads();

    int q = lane & 3, r = lane >> 2;
    int mw = w >> 1, nw = w & 1;
    int m0 = mw * 64, nb = nw * 32;

    float C[4][4][4];
    #pragma unroll
    for (int mi = 0; mi < 4; ++mi)
        #pragma unroll
        for (int ni = 0; ni < 4; ++ni)
            #pragma unroll
            for (int j = 0; j < 4; ++j) C[mi][ni][j] = 0.f;

    #pragma unroll
    for (int ks = 0; ks < 5; ++ks) {
        const uint4* bp = wS + ks * 296 + q * 74 + r * 9 + nw * 4;
        uint4 B0 = bp[0], B1 = bp[1], B2 = bp[2], B3 = bp[3];
        unsigned Bh0[2] = {B0.x, B0.y}, Bl0[2] = {B0.z, B0.w};
        unsigned Bh1[2] = {B1.x, B1.y}, Bl1[2] = {B1.z, B1.w};
        unsigned Bh2[2] = {B2.x, B2.y}, Bl2[2] = {B2.z, B2.w};
        unsigned Bh3[2] = {B3.x, B3.y}, Bl3[2] = {B3.z, B3.w};
        #pragma unroll
        for (int mi = 0; mi < 4; ++mi) {
            const unsigned* arow = aS2 + (m0 + mi * 16 + r) * 40 + (ks * 4 + q) * 2;
            uint2 a0 = *(const uint2*)(arow);
            uint2 a1 = *(const uint2*)(arow + 8 * 40);
            unsigned Ah[4] = {a0.x, a1.x, a0.y, a1.y};
            mma_f16(C[mi][0], Ah, Bh0); mma_f16(C[mi][0], Ah, Bl0);
            mma_f16(C[mi][1], Ah, Bh1); mma_f16(C[mi][1], Ah, Bl1);
            mma_f16(C[mi][2], Ah, Bh2); mma_f16(C[mi][2], Ah, Bl2);
            mma_f16(C[mi][3], Ah, Bh3); mma_f16(C[mi][3], Ah, Bl3);
        }
    }

    float bv[4][2];
    #pragma unroll
    for (int ni = 0; ni < 4; ++ni) {
        bv[ni][0] = __ldg(b1 + nb + ni * 8 + 2 * q);
        bv[ni][1] = __ldg(b1 + nb + ni * 8 + 2 * q + 1);
    }
    float cs[4][2], cq[4][2];
    #pragma unroll
    for (int ni = 0; ni < 4; ++ni) { cs[ni][0]=cs[ni][1]=cq[ni][0]=cq[ni][1]=0.f; }

    __syncthreads();   // A tile dead; reuse aS2 as output tile (stride 36 words)

    #pragma unroll
    for (int mi = 0; mi < 4; ++mi)
        #pragma unroll
        for (int half = 0; half < 2; ++half) {
            int rowl = m0 + mi * 16 + half * 8 + r;
            int e = e0 + rowl;
            if (e < E) {
                unsigned* hp = aS2 + rowl * 36 + (nb >> 1);
                #pragma unroll
                for (int ni = 0; ni < 4; ++ni) {
                    float v0 = C[mi][ni][half * 2 + 0] + bv[ni][0];
                    float v1 = C[mi][ni][half * 2 + 1] + bv[ni][1];
                    __half2 hh = __floats2half2_rn(v0, v1);
                    hp[ni * 4 + q] = *(unsigned*)&hh;
                    float2 qv = __half22float2(hh);
                    cs[ni][0] += qv.x; cs[ni][1] += qv.y;
                    cq[ni][0] += qv.x * qv.x; cq[ni][1] += qv.y * qv.y;
                }
            }
        }
    #pragma unroll
    for (int ni = 0; ni < 4; ++ni)
        #pragma unroll
        for (int j = 0; j < 2; ++j) {
            #pragma unroll
            for (int off = 4; off <= 16; off <<= 1) {
                cs[ni][j] += __shfl_xor_sync(0xffffffffu, cs[ni][j], off);
                cq[ni][j] += __shfl_xor_sync(0xffffffffu, cq[ni][j], off);
            }
        }
    if (lane < 4) {
        #pragma unroll
        for (int ni = 0; ni < 4; ++ni) {
            int col = nb + ni * 8 + 2 * lane;
            atomicAdd(&sstat[col],          cs[ni][0]);
            atomicAdd(&sstat[col + 1],      cs[ni][1]);
            atomicAdd(&sstat[64 + col],     cq[ni][0]);
            atomicAdd(&sstat[64 + col + 1], cq[ni][1]);
        }
    }
    __syncthreads();

    // coalesced h1 store: 8 threads per 128B row
    #pragma unroll
    for (int it = 0; it < 8; ++it) {
        int idx = t + it * 256;
        int row = idx >> 3, c = idx & 7;
        int e = e0 + row;
        if (e < E) {
            uint4 v = *(const uint4*)(aS2 + row * 36 + c * 4);
            *(uint4*)(g_h1 + (size_t)e * 64 + c * 8) = v;
        }
    }
    if (t < 128) atomicAdd(&g_stats[t], sstat[t]);
}

// ---------------- K3: gather-aggregate, fp16-packed output ------------------
__global__ __launch_bounds__(256)
void k_gather(const float* __restrict__ g1, const float* __restrict__ be1,
              int N, float invE)
{
    __shared__ float a1s[64], c1s[64];
    int t = threadIdx.x;
    if (t < 64) {
        float m = g_stats[t] * invE;
        float v = g_stats[64 + t] * invE - m * m;
        float a = g1[t] * rsqrtf(v + EPS);
        a1s[t] = a;
        c1s[t] = be1[t] - m * a;
    }
    __syncthreads();
    int w = t >> 5, lane = t & 31;
    int n = blockIdx.x * 8 + w;
    if (n >= N) return;
    int beg = g_off[n], end = g_off[n + 1];
    int deg = end - beg;
    float a0 = a1s[2 * lane], a1v = a1s[2 * lane + 1];
    float c0 = c1s[2 * lane], c1v = c1s[2 * lane + 1];
    float acc0 = 0.f, acc1 = 0.f;
    for (int base = beg; base < end; base += 32) {
        int cnt = min(32, end - base);
        int eid = (lane < cnt) ? g_eidx[base + lane] : 0;
        for (int j = 0; j < cnt; ++j) {
            int e = __shfl_sync(0xffffffffu, eid, j);
            __half2 hv = *(const __half2*)(g_h1 + (size_t)e * 64 + 2 * lane);
            float2 f = __half22float2(hv);
            acc0 += fmaxf(fmaf(f.x, a0, c0), 0.f);
            acc1 += fmaxf(fmaf(f.y, a1v, c1v), 0.f);
        }
    }
    float rcp = 1.f / fmaxf((float)deg, 1.f);
    // pair index p = lane; frag word index js = ks*8 + qq*2 + slot
    int js = (lane >> 3) * 8 + (lane & 3) * 2 + ((lane >> 2) & 1);
    g_spreP[(size_t)n * 32 + js] = packh(acc0 * rcp, acc1 * rcp);
    if (lane == 0) g_ind[n] = (deg > 0) ? 1.f : 0.f;
}

// ---------------- K4: node lin via fp16 mma + BN stats ----------------------
__global__ __launch_bounds__(256, 3)
void k_node1(const float* __restrict__ x, const float* __restrict__ b3, int N)
{
    extern __shared__ uint4 sm4[];
    uint4* wS = sm4;                              // 1480 uint4
    unsigned* aS2 = (unsigned*)(sm4 + 1480);      // 128 * 40 u32
    float* sstat = (float*)(aS2 + 128 * 40);      // 128
    float* indS  = sstat + 128;                   // 128
    int t = threadIdx.x;
    int lane = t & 31, w = t >> 5;
    int n0 = blockIdx.x * 128;

    for (int i = t; i < 1480; i += 256) wS[i] = g_wpkB[i];

    // staging: direct packed uint2 copy (bit-identical to old packh path)
    #pragma unroll
    for (int it = 0; it < 8; ++it) {
        int idx = t + it * 256;
        int erow = idx >> 4, j = idx & 15;
        uint2 hv = make_uint2(0u, 0u);
        if (n0 + erow < N)
            hv = *(const uint2*)(g_spreP + (size_t)(n0 + erow) * 32 + 2 * j);
        *(uint2*)(aS2 + erow * 40 + 2 * j) = hv;
    }
    if (t < 128) {
        int n = n0 + t;
        float x0 = 0.f, x1 = 0.f, x2 = 0.f, ind = 0.f;
        if (n < N) {
            x0 = x[n * 3]; x1 = x[n * 3 + 1]; x2 = x[n * 3 + 2];
            ind = g_ind[n];
        }
        unsigned* ap = aS2 + t * 40 + 32;
        *(uint2*)(ap + 0) = make_uint2(packh(x0, x1), 0u);
        *(uint2*)(ap + 2) = make_uint2(packh(x2, 0.f), 0u);
        *(uint2*)(ap + 4) = make_uint2(0u, 0u);
        *(uint2*)(ap + 6) = make_uint2(0u, 0u);
        sstat[t] = 0.f;
        indS[t] = ind;
    }
    __syncthreads();

    int q = lane & 3, r = lane >> 2;
    int mw = w >> 1, nw = w & 1;
    int m0 = mw * 32, nb = nw * 32;

    float C[2][4][4];
    #pragma unroll
    for (int mi = 0; mi < 2; ++mi)
        #pragma unroll
        for (int ni = 0; ni < 4; ++ni)
            #pragma unroll
            for (int j = 0; j < 4; ++j) C[mi][ni][j] = 0.f;

    mma_mainloop(aS2, wS, m0, nw, q, r, C);

    float bv[4][2], bbv[4][2];
    #pragma unroll
    for (int ni = 0; ni < 4; ++ni) {
        int col = nb + ni * 8 + 2 * q;
        bv[ni][0] = __ldg(b3 + col);     bv[ni][1] = __ldg(b3 + col + 1);
        bbv[ni][0] = g_bb[col];          bbv[ni][1] = g_bb[col + 1];
    }
    float cs[4][2], cq[4][2];
    #pragma unroll
    for (int ni = 0; ni < 4; ++ni) { cs[ni][0]=cs[ni][1]=cq[ni][0]=cq[ni][1]=0.f; }

    #pragma unroll
    for (int mi = 0; mi < 2; ++mi)
        #pragma unroll
        for (int half = 0; half < 2; ++half) {
            int rowl = m0 + mi * 16 + half * 8 + r;
            int n = n0 + rowl;
            if (n < N) {
                float ind = indS[rowl];
                __half* hp = g_o1h + (size_t)n * 64 + nb;
                #pragma unroll
                for (int ni = 0; ni < 4; ++ni) {
                    float v0 = C[mi][ni][half * 2 + 0] + bv[ni][0] + ind * bbv[ni][0];
                    float v1 = C[mi][ni][half * 2 + 1] + bv[ni][1] + ind * bbv[ni][1];
                    __half2 hh = __floats2half2_rn(v0, v1);
                    *(__half2*)(hp + ni * 8 + 2 * q) = hh;
                    float2 qv = __half22float2(hh);
                    cs[ni][0] += qv.x; cs[ni][1] += qv.y;
                    cq[ni][0] += qv.x * qv.x; cq[ni][1] += qv.y * qv.y;
                }
            }
        }
    #pragma unroll
    for (int ni = 0; ni < 4; ++ni)
        #pragma unroll
        for (int j = 0; j < 2; ++j) {
            #pragma unroll
            for (int off = 4; off <= 16; off <<= 1) {
                cs[ni][j] += __shfl_xor_sync(0xffffffffu, cs[ni][j], off);
                cq[ni][j] += __shfl_xor_sync(0xffffffffu, cq[ni][j], off);
            }
        }
    if (lane < 4) {
        #pragma unroll
        for (int ni = 0; ni < 4; ++ni) {
            int col = nb + ni * 8 + 2 * lane;
            atomicAdd(&sstat[col],          cs[ni][0]);
            atomicAdd(&sstat[col + 1],      cs[ni][1]);
            atomicAdd(&sstat[64 + col],     cq[ni][0]);
            atomicAdd(&sstat[64 + col + 1], cq[ni][1]);
        }
    }
    __syncthreads();
    if (t < 128) atomicAdd(&g_stats[128 + t], sstat[t]);
}

// ---------------- K6: out = relu(bn(o1)) @ w4 + b4 via fp16 mma -------------
__global__ __launch_bounds__(256, 3)
void k_node2(const float* __restrict__ b4, const float* __restrict__ g3,
             const float* __restrict__ be3, float* __restrict__ out,
             int N, float invN)
{
    extern __shared__ uint4 sm4[];
    uint4* wS = sm4;                              // 1480 uint4
    unsigned* aS2 = (unsigned*)(sm4 + 1480);      // 128 * 40 u32
    float* a3s = (float*)(aS2 + 128 * 40);        // 64
    float* c3s = a3s + 64;                        // 64
    int t = threadIdx.x;
    int lane = t & 31, w = t >> 5;
    int n0 = blockIdx.x * 128;

    for (int i = t; i < 1480; i += 256) wS[i] = g_wpkC[i];
    if (t < 64) {
        float m = g_stats[128 + t] * invN;
        float v = g_stats[192 + t] * invN - m * m;
        float a = g3[t] * rsqrtf(v + EPS);
        a3s[t] = a;
        c3s[t] = be3[t] - m * a;
    }
    __syncthreads();

    #pragma unroll
    for (int it = 0; it < 8; ++it) {
        int idx = t + it * 256;
        int erow = idx >> 4, j = idx & 15;
        int ks = j >> 2, qq = j & 3;
        float2 f0 = make_float2(0.f, 0.f), f1 = make_float2(0.f, 0.f);
        if (n0 + erow < N) {
            const unsigned* orow = (const unsigned*)(g_o1h + (size_t)(n0 + erow) * 64);
            int p0 = ks * 8 + qq;
            float2 e0 = h2f(orow[p0]);
            float2 e1 = h2f(orow[p0 + 4]);
            int k0 = 2 * p0, k1 = 2 * p0 + 8;
            f0.x = fmaxf(fmaf(e0.x, a3s[k0],     c3s[k0]),     0.f);
            f0.y = fmaxf(fmaf(e0.y, a3s[k0 + 1], c3s[k0 + 1]), 0.f);
            f1.x = fmaxf(fmaf(e1.x, a3s[k1],     c3s[k1]),     0.f);
            f1.y = fmaxf(fmaf(e1.y, a3s[k1 + 1], c3s[k1 + 1]), 0.f);
        }
        *(uint2*)(aS2 + erow * 40 + 2 * j) = make_uint2(packh(f0.x, f0.y), packh(f1.x, f1.y));
    }
    if (t < 128) {
        unsigned* ap = aS2 + t * 40 + 32;
        *(uint2*)(ap + 0) = make_uint2(0u, 0u);
        *(uint2*)(ap + 2) = make_uint2(0u, 0u);
        *(uint2*)(ap + 4) = make_uint2(0u, 0u);
        *(uint2*)(ap + 6) = make_uint2(0u, 0u);
    }
    __syncthreads();

    int q = lane & 3, r = lane >> 2;
    int mw = w >> 1, nw = w & 1;
    int m0 = mw * 32, nb = nw * 32;

    float C[2][4][4];
    #pragma unroll
    for (int mi = 0; mi < 2; ++mi)
        #pragma unroll
        for (int ni = 0; ni < 4; ++ni)
            #pragma unroll
            for (int j = 0; j < 4; ++j) C[mi][ni][j] = 0.f;

    mma_mainloop(aS2, wS, m0, nw, q, r, C);

    float bv[4][2];
    #pragma unroll
    for (int ni = 0; ni < 4; ++ni) {
        bv[ni][0] = __ldg(b4 + nb + ni * 8 + 2 * q);
        bv[ni][1] = __ldg(b4 + nb + ni * 8 + 2 * q + 1);
    }
    #pragma unroll
    for (int mi = 0; mi < 2; ++mi)
        #pragma unroll
        for (int half = 0; half < 2; ++half) {
            int n = n0 + m0 + mi * 16 + half * 8 + r;
            if (n < N) {
                float* op = out + (size_t)n * 64 + nb;
                #pragma unroll
                for (int ni = 0; ni < 4; ++ni) {
                    float v0 = C[mi][ni][half * 2 + 0] + bv[ni][0];
                    float v1 = C[mi][ni][half * 2 + 1] + bv[ni][1];
                    *(float2*)(op + ni * 8 + 2 * q) = make_float2(v0, v1);
                }
            }
        }
}

// ---------------- host ------------------------------------------------------
extern "C" void kernel_launch(void* const* d_in, const int* in_sizes, int n_in,
                              void* d_out, int out_size)
{
    const float* x   = (const float*)d_in[0];
    const void*  ei  = d_in[1];
    const float* ea  = (const float*)d_in[2];
    const float* w1  = (const float*)d_in[5];
    const float* b1  = (const float*)d_in[6];
    const float* g1  = (const float*)d_in[7];
    const float* be1 = (const float*)d_in[8];
    const float* w2  = (const float*)d_in[9];
    const float* b2  = (const float*)d_in[10];
    const float* w3  = (const float*)d_in[11];
    const float* b3  = (const float*)d_in[12];
    const float* g3  = (const float*)d_in[13];
    const float* be3 = (const float*)d_in[14];
    const float* w4  = (const float*)d_in[15];
    const float* b4  = (const float*)d_in[16];
    int N = in_sizes[0] / 3;
    int E = in_sizes[2] / 64;

    static cudaStream_t s2 = nullptr;
    static cudaEvent_t evFork = nullptr, evJoin = nullptr;
    if (s2 == nullptr) {
        cudaStreamCreateWithFlags(&s2, cudaStreamNonBlocking);
        cudaEventCreateWithFlags(&evFork, cudaEventDisableTiming);
        cudaEventCreateWithFlags(&evJoin, cudaEventDisableTiming);
    }

    const int SMEM_K1 = 1480 * 16 + 256 * 40 * 4 + 128 * 4;               // 65152
    const int SMEM_K4 = 1480 * 16 + 128 * 40 * 4 + 256 * 4;               // 45184
    const int SMEM_K6 = 1480 * 16 + 128 * 40 * 4 + 128 * 4;               // 44672

    cudaFuncSetAttribute(k_edge,  cudaFuncAttributeMaxDynamicSharedMemorySize, SMEM_K1);
    cudaFuncSetAttribute(k_node1, cudaFuncAttributeMaxDynamicSharedMemorySize, SMEM_K4);
    cudaFuncSetAttribute(k_node2, cudaFuncAttributeMaxDynamicSharedMemorySize, SMEM_K6);

    void *p_stats, *p_off;
    cudaGetSymbolAddress(&p_stats, g_stats);
    cudaGetSymbolAddress(&p_off,   g_off);

    int G1 = (N + 1023) / 1024;

    // main stream: stats memset + w1 pack (+dtype detect), then fork
    cudaMemsetAsync(p_stats, 0, 256 * sizeof(float), 0);                  // slot 0
    k_prep<<<1, 256>>>(w1, (const int*)ei);                               // slot 1
    cudaEventRecord(evFork, 0);
    cudaStreamWaitEvent(s2, evFork, 0);

    // side stream: node-weight prep + CSR front half (submitted before k_edge
    // so k_edge lands at global launch slot 5 for ncu -s 5 -c 1)
    k_prep2<<<1, 256, 0, s2>>>(w2, w3, b2, w4);                           // slot 2
    cudaMemsetAsync(p_off, 0, (size_t)(N + 1) * sizeof(int), s2);         // slot 3
    k_hist<<<(E + 255) / 256, 256, 0, s2>>>(ei, E);                       // slot 4

    // main stream: edge GEMM (the long pole)                              // slot 5
    k_edge<<<(E + 255) / 256, 256, SMEM_K1>>>(x, ei, ea, b1, E);

    // side stream: CSR back half
    k_scan1<<<G1, 1024, 0, s2>>>(N);
    k_scan2<<<1, 512, 0, s2>>>(G1);
    k_scan3<<<G1, 1024, 0, s2>>>(N, E);
    k_fill<<<(E + 255) / 256, 256, 0, s2>>>(ei, E);
    cudaEventRecord(evJoin, s2);

    // join, then aggregate + node MLP
    cudaStreamWaitEvent(0, evJoin, 0);
    k_gather<<<(N + 7) / 8, 256>>>(g1, be1, N, 1.f / (float)E);
    k_node1<<<(N + 127) / 128, 256, SMEM_K4>>>(x, b3, N);
    k_node2<<<(N + 127) / 128, 256, SMEM_K6>>>(b4, g3, be3, (float*)d_out, N, 1.f / (float)N);
}